// round 5
// baseline (speedup 1.0000x reference)
#include <cuda_runtime.h>
#include <cstdint>

// S3FD anchor assignment: spatial binning via atomic-free counting sort.
//   k_hist:     per-anchor cell id (16x16 grid, 64px cells, by center) +
//               per-block smem histogram -> g_blockhist[cell][block]
//   k_cellscan: per-cell exclusive scan of block counts (in place) + cell totals
//   k_offs:     scan cell totals -> bin offsets; build 1024-anchor chunk worklist
//   k_gtlist:   PARALLEL per-cell GT list (1 block/cell, 1 thread/GT, order-
//               preserving ballot compaction so list stays in increasing GT order
//               -> strict-> argmax keeps first max like the reference).
//               Blocks 0-2 also zero g_top3 (replaces a memset node).
//   k_scatter:  smem cursors = offs[c] + blockbase; smem-atomic rank -> write
//   k_main:     per-chunk IoU vs cell's GT list; max/argmax -> stage-1 assign;
//               per-GT top-3 via lock-free atomicMax cascade (smem -> global)
//   k2_resolve: per-GT claims -> <=768-entry smem list -> per-anchor max-gt
//               resolution -> direct overwrite of out (replaces forced[]+k3).
// Output dtype float32 (small ints as floats). IoU math uses __f*_rn intrinsics:
// bit-identical to the float32 reference. Pruned pairs always have inter==0 and
// cannot affect strict-> argmax (best init 0) or the iou>0-gated top-3.

#define TPB 256
#define APT 4
#define CHUNK (TPB * APT)      // 1024 anchors per work chunk
#define MAXM 256               // >= n_gt (200)
#define MAXN (1 << 20)         // >= n_anchor (500000)
#define NB_MAX (MAXN / TPB)
#define NCELL 256
#define GRIDW 16
#define CELL_PX 64.0f
#define EXPAND 65.0f           // 64 max anchor half-extent + 1px rounding slack

__device__ unsigned char g_cellid[MAXN];
__device__ int g_blockhist[NCELL * NB_MAX];     // cell-major: [cell * nb + block]
__device__ int g_celltotal[NCELL];
__device__ int g_offs[NCELL];
__device__ int g_nwork;
__device__ int4 g_work[NCELL + MAXN / CHUNK + 2];
__device__ int g_binned[MAXN];                  // binned pos -> original anchor idx
__device__ float4 g_bbox[MAXN];                 // binned anchor boxes (coalesced)
__device__ int g_gtcnt[NCELL];
__device__ int g_gtlist[NCELL * MAXM];
__device__ unsigned long long g_top3[MAXM * 3];

// Lock-free top-3 insert: slots monotone non-decreasing under atomicMax; the
// displaced minimum cascades down. Keys distinct (low bits = ~anchor idx), so
// final state is the exact sorted top-3 of all inserted keys.
__device__ __forceinline__ void cascade_insert(unsigned long long* s, unsigned long long v) {
#pragma unroll
    for (int i = 0; i < 3; i++) {
        unsigned long long old = atomicMax(&s[i], v);
        v = old < v ? old : v;
        if (v == 0ull) return;
    }
}

__device__ __forceinline__ int cell_of(float4 a) {
    int cx = min(GRIDW - 1, max(0, (int)((a.x + a.z) * (0.5f / CELL_PX))));
    int cy = min(GRIDW - 1, max(0, (int)((a.y + a.w) * (0.5f / CELL_PX))));
    return cy * GRIDW + cx;
}

__global__ void __launch_bounds__(TPB) k_hist(const float4* __restrict__ anc, int n) {
    __shared__ int h[NCELL];
    const int t = threadIdx.x, b = blockIdx.x;
    h[t] = 0;
    __syncthreads();
    int i = b * TPB + t;
    if (i < n) {
        int c = cell_of(anc[i]);
        g_cellid[i] = (unsigned char)c;
        atomicAdd(&h[c], 1);
    }
    __syncthreads();
    g_blockhist[t * gridDim.x + b] = h[t];
}

// Block c: exclusive-scan its nb block-counts in place; emit cell total.
__global__ void __launch_bounds__(TPB) k_cellscan(int nb) {
    __shared__ int sums[TPB];
    const int c = blockIdx.x, t = threadIdx.x;
    const int per = (nb + TPB - 1) / TPB;
    int* row = &g_blockhist[c * nb];
    int s = 0;
    for (int k = 0; k < per; k++) {
        int idx = t * per + k;
        if (idx < nb) s += row[idx];
    }
    sums[t] = s;
    __syncthreads();
    for (int d = 1; d < TPB; d <<= 1) {
        int x = (t >= d) ? sums[t - d] : 0; __syncthreads();
        sums[t] += x; __syncthreads();
    }
    int run = sums[t] - s;
    for (int k = 0; k < per; k++) {
        int idx = t * per + k;
        if (idx < nb) { int v = row[idx]; row[idx] = run; run += v; }
    }
    if (t == TPB - 1) g_celltotal[c] = sums[t];
}

// One block: scan cell totals -> g_offs; build chunk worklist.
__global__ void __launch_bounds__(NCELL) k_offs() {
    __shared__ int s[NCELL];
    const int t = threadIdx.x;
    int v = g_celltotal[t];
    s[t] = v; __syncthreads();
    for (int d = 1; d < NCELL; d <<= 1) {
        int x = (t >= d) ? s[t - d] : 0; __syncthreads();
        s[t] += x; __syncthreads();
    }
    int excl = s[t] - v;
    g_offs[t] = excl;
    int ch = (v + CHUNK - 1) / CHUNK;
    __syncthreads();
    s[t] = ch; __syncthreads();
    for (int d = 1; d < NCELL; d <<= 1) {
        int x = (t >= d) ? s[t - d] : 0; __syncthreads();
        s[t] += x; __syncthreads();
    }
    int chexcl = s[t] - ch;
    if (t == NCELL - 1) g_nwork = s[t];
    for (int k = 0; k < ch; k++)
        g_work[chexcl + k] = make_int4(t, excl + k * CHUNK, min(CHUNK, v - k * CHUNK), 0);
}

// One block per cell; thread t tests GT t. Order-preserving compaction keeps the
// GT list sorted by index (reference tie-break for argmax). Blocks 0-2 zero g_top3.
__global__ void __launch_bounds__(TPB) k_gtlist(const float4* __restrict__ gts, int m) {
    __shared__ int wcnt[TPB / 32];
    const int c = blockIdx.x, t = threadIdx.x;
    if (c < 3) {
        int i = c * TPB + t;
        if (i < MAXM * 3) g_top3[i] = 0ull;
    }
    float cx0 = (c & (GRIDW - 1)) * CELL_PX - EXPAND;
    float cx1 = (c & (GRIDW - 1)) * CELL_PX + CELL_PX + EXPAND;
    float cy0 = (c >> 4) * CELL_PX - EXPAND;
    float cy1 = (c >> 4) * CELL_PX + CELL_PX + EXPAND;
    bool p = false;
    if (t < m) {
        float4 G = gts[t];
        p = (G.x <= cx1 && G.z >= cx0 && G.y <= cy1 && G.w >= cy0);
    }
    unsigned b = __ballot_sync(0xffffffffu, p);
    int wid = t >> 5, lane = t & 31;
    int rank = __popc(b & ((1u << lane) - 1u));
    if (lane == 0) wcnt[wid] = __popc(b);
    __syncthreads();
    int base = 0;
    for (int w = 0; w < wid; w++) base += wcnt[w];
    if (p) g_gtlist[c * MAXM + base + rank] = t;
    if (t == 0) {
        int tot = 0;
        for (int w = 0; w < TPB / 32; w++) tot += wcnt[w];
        g_gtcnt[c] = tot;
    }
}

__global__ void __launch_bounds__(TPB) k_scatter(const float4* __restrict__ anc, int n, int nb) {
    __shared__ int cur[NCELL];
    const int t = threadIdx.x, b = blockIdx.x;
    cur[t] = g_offs[t] + g_blockhist[t * nb + b];
    __syncthreads();
    int i = b * TPB + t;
    if (i < n) {
        float4 a = anc[i];
        int c = g_cellid[i];
        int pos = atomicAdd(&cur[c], 1);
        g_bbox[pos] = a;
        g_binned[pos] = i;
    }
}

__global__ void __launch_bounds__(TPB) k_main(
    const float4* __restrict__ gts, float* __restrict__ out,
    unsigned long long* __restrict__ gtop)
{
    __shared__ float4 sgc[MAXM];
    __shared__ float sga[MAXM];
    __shared__ int sgi[MAXM];
    __shared__ unsigned long long stop[MAXM * 3];

    if (blockIdx.x >= g_nwork) return;
    int4 w = g_work[blockIdx.x];
    const int cell = w.x, astart = w.y, alen = w.z;
    const int tid = threadIdx.x;

    const int cnt = g_gtcnt[cell];
    if (tid < cnt) {
        int gi = g_gtlist[cell * MAXM + tid];
        float4 G = gts[gi];
        sgc[tid] = G;
        sga[tid] = __fmul_rn(__fsub_rn(G.z, G.x), __fsub_rn(G.w, G.y));
        sgi[tid] = gi;
    }
    for (int i = tid; i < MAXM * 3; i += TPB) stop[i] = 0ull;
    __syncthreads();

    float ax1[APT], ay1[APT], ax2[APT], ay2[APT], aar[APT], best[APT];
    int bc[APT], aidx[APT];
    bool act[APT];
#pragma unroll
    for (int j = 0; j < APT; j++) {
        int p = tid + j * TPB;
        act[j] = p < alen;
        // Inactive lanes get a far sentinel box: inter==0 vs any GT, area 0.
        float4 a = act[j] ? g_bbox[astart + p] : make_float4(4e9f, 4e9f, 4e9f, 4e9f);
        aidx[j] = act[j] ? g_binned[astart + p] : 0;
        ax1[j] = a.x; ay1[j] = a.y; ax2[j] = a.z; ay2[j] = a.w;
        aar[j] = __fmul_rn(__fsub_rn(a.z, a.x), __fsub_rn(a.w, a.y));
        best[j] = 0.f;   // all-zero row -> ref argmax 0
        bc[j] = 0;
    }

    // Stale-read skip gate: slot-2 high word is monotone non-decreasing; a racy
    // 32-bit read is always a safe lower bound.
    const unsigned* stop_hi = (const unsigned*)stop;

    for (int c = 0; c < cnt; c++) {
        float4 G = sgc[c];
        float ga = sga[c];
        unsigned min_hi = stop_hi[(c * 3 + 2) * 2 + 1];
#pragma unroll
        for (int j = 0; j < APT; j++) {
            float ltx = fmaxf(ax1[j], G.x), lty = fmaxf(ay1[j], G.y);
            float rbx = fminf(ax2[j], G.z), rby = fminf(ay2[j], G.w);
            float wd = fmaxf(__fsub_rn(rbx, ltx), 0.f);
            float ht = fmaxf(__fsub_rn(rby, lty), 0.f);
            float inter = __fmul_rn(wd, ht);
            if (inter > 0.f) {
                float denom = __fsub_rn(__fadd_rn(aar[j], ga), inter);
                float iou = __fdiv_rn(inter, denom);    // IEEE rn, matches reference
                if (iou > best[j]) { best[j] = iou; bc[j] = c; }
                unsigned ib = __float_as_uint(iou);
                if (ib >= min_hi) {
                    unsigned long long key =
                        ((unsigned long long)ib << 32) | (unsigned)(~(unsigned)aidx[j]);
                    cascade_insert(&stop[c * 3], key);
                    min_hi = stop_hi[(c * 3 + 2) * 2 + 1];
                }
            }
        }
    }

#pragma unroll
    for (int j = 0; j < APT; j++) {
        if (act[j]) {
            float r = -2.0f;
            if (best[j] < 0.3f) r = -1.0f;
            if (best[j] > 0.5f) r = (float)sgi[bc[j]];
            out[aidx[j]] = r;
        }
    }

    __syncthreads();
    const unsigned* gtop_hi = (const unsigned*)gtop;
    for (int i = tid; i < cnt * 3; i += TPB) {
        unsigned long long v = stop[i];
        if (!v) continue;
        int orig = sgi[i / 3];
        unsigned gm = gtop_hi[(orig * 3 + 2) * 2 + 1];
        if ((unsigned)(v >> 32) >= gm) cascade_insert(&gtop[orig * 3], v);
    }
}

// One block. Build claim list (anchor, gt) in smem (<= 3*m entries), resolve
// per-anchor winner = max claiming gt (reference scatter-max), write into out.
__global__ void __launch_bounds__(TPB) k2_resolve(
    const unsigned long long* __restrict__ gtop, int m, float* __restrict__ out)
{
    __shared__ int cnt;
    __shared__ int ea[MAXM * 3];
    __shared__ int eg[MAXM * 3];
    const int t = threadIdx.x;
    if (t == 0) cnt = 0;
    __syncthreads();
    if (t < m) {
        unsigned long long s0 = gtop[t * 3 + 0];
        unsigned long long s1 = gtop[t * 3 + 1];
        unsigned long long s2 = gtop[t * 3 + 2];
        float v0 = __uint_as_float((unsigned)(s0 >> 32));
        float v1 = __uint_as_float((unsigned)(s1 >> 32));
        float v2 = __uint_as_float((unsigned)(s2 >> 32));
        int npos = (v0 > 0.5f) + (v1 > 0.5f) + (v2 > 0.5f);
        bool low = npos < 3;
        // k==0 always claims. Empty slot 0 = all-zero row: ref top_k rank0 -> anchor 0.
        int a0 = s0 ? (int)(~(unsigned)s0) : 0;
        int e = atomicAdd(&cnt, 1); ea[e] = a0; eg[e] = t;
        if (low) {
            if (s1 && v1 > 0.1f) { e = atomicAdd(&cnt, 1); ea[e] = (int)(~(unsigned)s1); eg[e] = t; }
            if (s2 && v2 > 0.1f) { e = atomicAdd(&cnt, 1); ea[e] = (int)(~(unsigned)s2); eg[e] = t; }
        }
    }
    __syncthreads();
    const int E = cnt;
    for (int j = t; j < E; j += TPB) {
        int aj = ea[j], gj = eg[j];
        bool win = true;
        for (int k = 0; k < E; k++)
            if (ea[k] == aj && eg[k] > gj) { win = false; break; }
        if (win) out[aj] = (float)gj;
    }
}

extern "C" void kernel_launch(void* const* d_in, const int* in_sizes, int n_in,
                              void* d_out, int out_size)
{
    const float4* anc = (const float4*)d_in[0];
    const float4* gts = (const float4*)d_in[1];
    int n = in_sizes[0] / 4;
    int m = in_sizes[1] / 4;
    float* out = (float*)d_out;

    void* ptop = nullptr;
    cudaGetSymbolAddress(&ptop, g_top3);

    int nb = (n + TPB - 1) / TPB;
    k_hist<<<nb, TPB>>>(anc, n);
    k_cellscan<<<NCELL, TPB>>>(nb);
    k_offs<<<1, NCELL>>>();
    k_gtlist<<<NCELL, TPB>>>(gts, m);
    k_scatter<<<nb, TPB>>>(anc, n, nb);
    int mblocks = NCELL + (n + CHUNK - 1) / CHUNK;
    k_main<<<mblocks, TPB>>>(gts, out, (unsigned long long*)ptop);
    k2_resolve<<<1, TPB>>>((const unsigned long long*)ptop, m, out);
}

// round 6
// speedup vs baseline: 1.2119x; 1.2119x over previous
#include <cuda_runtime.h>
#include <cstdint>

// S3FD anchor assignment: spatial binning via atomic-free counting sort.
//   k_hist:    per-anchor cell id (16x16 grid, 64px cells, by center) +
//              per-block smem histogram -> g_blockhist[cell][block]
//   k_phase2:  blocks [0,NCELL): per-cell exclusive scan of block counts + totals
//              blocks [NCELL,2*NCELL): per-cell GT list (1 thread/GT, order-
//              preserving ballot compaction -> list stays in increasing GT order,
//              preserving the reference first-max tie-break) + zero g_top3
//   k_offs:    scan cell totals -> bin offsets; build 1024-anchor chunk worklist
//   k_scatter: smem cursors = offs[c] + blockbase; smem-atomic rank -> write
//   k_main:    per-chunk IoU vs cell's GT list; max/argmax -> stage-1 assign;
//              per-GT top-3 via lock-free atomicMax cascade (smem -> global)
//   k2_resolve:per-GT claims -> smem list -> per-anchor max-gt winner -> out
// Output dtype float32 (small ints as floats). IoU math uses __f*_rn intrinsics:
// bit-identical to the float32 reference. Pruned pairs always have inter==0 and
// cannot affect strict-> argmax (best init 0) or the iou>0-gated top-3.

#define TPB 256
#define APT 4
#define CHUNK (TPB * APT)      // 1024 anchors per work chunk
#define MAXM 256               // >= n_gt (200)
#define MAXN (1 << 20)         // >= n_anchor (500000)
#define NB_MAX (MAXN / TPB)
#define NCELL 256
#define GRIDW 16
#define CELL_PX 64.0f
#define EXPAND 65.0f           // 64 max anchor half-extent + 1px rounding slack

__device__ unsigned char g_cellid[MAXN];
__device__ int g_blockhist[NCELL * NB_MAX];     // cell-major: [cell * nb + block]
__device__ int g_celltotal[NCELL];
__device__ int g_offs[NCELL];
__device__ int g_nwork;
__device__ int4 g_work[NCELL + MAXN / CHUNK + 2];
__device__ int g_binned[MAXN];                  // binned pos -> original anchor idx
__device__ float4 g_bbox[MAXN];                 // binned anchor boxes (coalesced)
__device__ int g_gtcnt[NCELL];
__device__ int g_gtlist[NCELL * MAXM];
__device__ unsigned long long g_top3[MAXM * 3];

// Lock-free top-3 insert: slots monotone non-decreasing under atomicMax; the
// displaced minimum cascades down. Keys distinct (low bits = ~anchor idx), so
// the final state is the exact sorted top-3 of all inserted keys.
__device__ __forceinline__ void cascade_insert(unsigned long long* s, unsigned long long v) {
#pragma unroll
    for (int i = 0; i < 3; i++) {
        unsigned long long old = atomicMax(&s[i], v);
        v = old < v ? old : v;
        if (v == 0ull) return;
    }
}

__device__ __forceinline__ int cell_of(float4 a) {
    int cx = min(GRIDW - 1, max(0, (int)((a.x + a.z) * (0.5f / CELL_PX))));
    int cy = min(GRIDW - 1, max(0, (int)((a.y + a.w) * (0.5f / CELL_PX))));
    return cy * GRIDW + cx;
}

__global__ void __launch_bounds__(TPB) k_hist(const float4* __restrict__ anc, int n) {
    __shared__ int h[NCELL];
    const int t = threadIdx.x, b = blockIdx.x;
    h[t] = 0;
    __syncthreads();
    int i = b * TPB + t;
    if (i < n) {
        int c = cell_of(anc[i]);
        g_cellid[i] = (unsigned char)c;
        atomicAdd(&h[c], 1);
    }
    __syncthreads();
    g_blockhist[t * gridDim.x + b] = h[t];
}

// Fused: blocks [0,NCELL) do per-cell scan of block counts; blocks
// [NCELL,2*NCELL) build per-cell GT lists and zero g_top3.
__global__ void __launch_bounds__(TPB) k_phase2(int nb, const float4* __restrict__ gts, int m) {
    __shared__ int sh[TPB];
    const int t = threadIdx.x;
    if (blockIdx.x < NCELL) {
        const int c = blockIdx.x;
        const int per = (nb + TPB - 1) / TPB;
        int* row = &g_blockhist[c * nb];
        int s = 0;
        for (int k = 0; k < per; k++) {
            int idx = t * per + k;
            if (idx < nb) s += row[idx];
        }
        sh[t] = s;
        __syncthreads();
        for (int d = 1; d < TPB; d <<= 1) {
            int x = (t >= d) ? sh[t - d] : 0; __syncthreads();
            sh[t] += x; __syncthreads();
        }
        int run = sh[t] - s;
        for (int k = 0; k < per; k++) {
            int idx = t * per + k;
            if (idx < nb) { int v = row[idx]; row[idx] = run; run += v; }
        }
        if (t == TPB - 1) g_celltotal[c] = sh[t];
    } else {
        const int c = blockIdx.x - NCELL;
        if (c < 3) {
            int i = c * TPB + t;
            if (i < MAXM * 3) g_top3[i] = 0ull;
        }
        float cx0 = (c & (GRIDW - 1)) * CELL_PX - EXPAND;
        float cx1 = (c & (GRIDW - 1)) * CELL_PX + CELL_PX + EXPAND;
        float cy0 = (c >> 4) * CELL_PX - EXPAND;
        float cy1 = (c >> 4) * CELL_PX + CELL_PX + EXPAND;
        bool p = false;
        if (t < m) {
            float4 G = gts[t];
            p = (G.x <= cx1 && G.z >= cx0 && G.y <= cy1 && G.w >= cy0);
        }
        unsigned b = __ballot_sync(0xffffffffu, p);
        int wid = t >> 5, lane = t & 31;
        int rank = __popc(b & ((1u << lane) - 1u));
        if (lane == 0) sh[wid] = __popc(b);
        __syncthreads();
        int base = 0;
        for (int w = 0; w < wid; w++) base += sh[w];
        if (p) g_gtlist[c * MAXM + base + rank] = t;
        if (t == 0) {
            int tot = 0;
            for (int w = 0; w < TPB / 32; w++) tot += sh[w];
            g_gtcnt[c] = tot;
        }
    }
}

// One block: scan cell totals -> g_offs; build chunk worklist.
__global__ void __launch_bounds__(NCELL) k_offs() {
    __shared__ int s[NCELL];
    const int t = threadIdx.x;
    int v = g_celltotal[t];
    s[t] = v; __syncthreads();
    for (int d = 1; d < NCELL; d <<= 1) {
        int x = (t >= d) ? s[t - d] : 0; __syncthreads();
        s[t] += x; __syncthreads();
    }
    int excl = s[t] - v;
    g_offs[t] = excl;
    int ch = (v + CHUNK - 1) / CHUNK;
    __syncthreads();
    s[t] = ch; __syncthreads();
    for (int d = 1; d < NCELL; d <<= 1) {
        int x = (t >= d) ? s[t - d] : 0; __syncthreads();
        s[t] += x; __syncthreads();
    }
    int chexcl = s[t] - ch;
    if (t == NCELL - 1) g_nwork = s[t];
    for (int k = 0; k < ch; k++)
        g_work[chexcl + k] = make_int4(t, excl + k * CHUNK, min(CHUNK, v - k * CHUNK), 0);
}

__global__ void __launch_bounds__(TPB) k_scatter(const float4* __restrict__ anc, int n, int nb) {
    __shared__ int cur[NCELL];
    const int t = threadIdx.x, b = blockIdx.x;
    cur[t] = g_offs[t] + g_blockhist[t * nb + b];
    __syncthreads();
    int i = b * TPB + t;
    if (i < n) {
        float4 a = anc[i];
        int c = g_cellid[i];
        int pos = atomicAdd(&cur[c], 1);
        g_bbox[pos] = a;
        g_binned[pos] = i;
    }
}

__global__ void __launch_bounds__(TPB) k_main(
    const float4* __restrict__ gts, float* __restrict__ out,
    unsigned long long* __restrict__ gtop)
{
    __shared__ float4 sgc[MAXM];
    __shared__ float sga[MAXM];
    __shared__ int sgi[MAXM];
    __shared__ unsigned long long stop[MAXM * 3];

    if (blockIdx.x >= g_nwork) return;
    int4 w = g_work[blockIdx.x];
    const int cell = w.x, astart = w.y, alen = w.z;
    const int tid = threadIdx.x;

    const int cnt = g_gtcnt[cell];
    if (tid < cnt) {
        int gi = g_gtlist[cell * MAXM + tid];
        float4 G = gts[gi];
        sgc[tid] = G;
        sga[tid] = __fmul_rn(__fsub_rn(G.z, G.x), __fsub_rn(G.w, G.y));
        sgi[tid] = gi;
    }
    for (int i = tid; i < cnt * 3; i += TPB) stop[i] = 0ull;   // only live slots
    __syncthreads();

    float ax1[APT], ay1[APT], ax2[APT], ay2[APT], aar[APT], best[APT];
    int bc[APT], aidx[APT];
    bool act[APT];
#pragma unroll
    for (int j = 0; j < APT; j++) {
        int p = tid + j * TPB;
        act[j] = p < alen;
        // Inactive lanes get a far sentinel box: inter==0 vs any GT.
        float4 a = act[j] ? g_bbox[astart + p] : make_float4(4e9f, 4e9f, 4e9f, 4e9f);
        aidx[j] = act[j] ? g_binned[astart + p] : 0;
        ax1[j] = a.x; ay1[j] = a.y; ax2[j] = a.z; ay2[j] = a.w;
        aar[j] = __fmul_rn(__fsub_rn(a.z, a.x), __fsub_rn(a.w, a.y));
        best[j] = 0.f;   // all-zero row -> ref argmax 0
        bc[j] = 0;
    }

    // Stale-read skip gate: slot-2 high word is monotone non-decreasing; a racy
    // 32-bit read is always a safe lower bound.
    const unsigned* stop_hi = (const unsigned*)stop;

    for (int c = 0; c < cnt; c++) {
        float4 G = sgc[c];
        float ga = sga[c];
        unsigned min_hi = stop_hi[(c * 3 + 2) * 2 + 1];
#pragma unroll
        for (int j = 0; j < APT; j++) {
            float ltx = fmaxf(ax1[j], G.x), lty = fmaxf(ay1[j], G.y);
            float rbx = fminf(ax2[j], G.z), rby = fminf(ay2[j], G.w);
            float wd = fmaxf(__fsub_rn(rbx, ltx), 0.f);
            float ht = fmaxf(__fsub_rn(rby, lty), 0.f);
            float inter = __fmul_rn(wd, ht);
            if (inter > 0.f) {
                float denom = __fsub_rn(__fadd_rn(aar[j], ga), inter);
                float iou = __fdiv_rn(inter, denom);    // IEEE rn, matches reference
                if (iou > best[j]) { best[j] = iou; bc[j] = c; }
                unsigned ib = __float_as_uint(iou);
                if (ib >= min_hi) {
                    unsigned long long key =
                        ((unsigned long long)ib << 32) | (unsigned)(~(unsigned)aidx[j]);
                    cascade_insert(&stop[c * 3], key);
                    min_hi = stop_hi[(c * 3 + 2) * 2 + 1];
                }
            }
        }
    }

#pragma unroll
    for (int j = 0; j < APT; j++) {
        if (act[j]) {
            float r = -2.0f;
            if (best[j] < 0.3f) r = -1.0f;
            if (best[j] > 0.5f) r = (float)sgi[bc[j]];
            out[aidx[j]] = r;
        }
    }

    __syncthreads();
    const unsigned* gtop_hi = (const unsigned*)gtop;
    for (int i = tid; i < cnt * 3; i += TPB) {
        unsigned long long v = stop[i];
        if (!v) continue;
        int orig = sgi[i / 3];
        unsigned gm = gtop_hi[(orig * 3 + 2) * 2 + 1];
        if ((unsigned)(v >> 32) >= gm) cascade_insert(&gtop[orig * 3], v);
    }
}

// One block. Build claim list (anchor, gt). Resolve per-anchor winner = max
// claiming gt (reference scatter-max order) via smem atomicMax keyed on the
// FIRST list occurrence of each anchor, then write winners into out.
__global__ void __launch_bounds__(TPB) k2_resolve(
    const unsigned long long* __restrict__ gtop, int m, float* __restrict__ out)
{
    __shared__ int cnt;
    __shared__ int ea[MAXM * 3];
    __shared__ int eg[MAXM * 3];
    __shared__ int win[MAXM * 3];
    const int t = threadIdx.x;
    if (t == 0) cnt = 0;
    __syncthreads();
    if (t < m) {
        unsigned long long s0 = gtop[t * 3 + 0];
        unsigned long long s1 = gtop[t * 3 + 1];
        unsigned long long s2 = gtop[t * 3 + 2];
        float v1 = __uint_as_float((unsigned)(s1 >> 32));
        float v2 = __uint_as_float((unsigned)(s2 >> 32));
        float v0 = __uint_as_float((unsigned)(s0 >> 32));
        int npos = (v0 > 0.5f) + (v1 > 0.5f) + (v2 > 0.5f);
        bool low = npos < 3;
        // k==0 always claims. Empty slot 0 = all-zero row: ref top_k rank0 -> anchor 0.
        int a0 = s0 ? (int)(~(unsigned)s0) : 0;
        int e = atomicAdd(&cnt, 1); ea[e] = a0; eg[e] = t;
        if (low) {
            if (s1 && v1 > 0.1f) { e = atomicAdd(&cnt, 1); ea[e] = (int)(~(unsigned)s1); eg[e] = t; }
            if (s2 && v2 > 0.1f) { e = atomicAdd(&cnt, 1); ea[e] = (int)(~(unsigned)s2); eg[e] = t; }
        }
    }
    __syncthreads();
    const int E = cnt;
    // rep[j] = first index k with ea[k]==ea[j]; atomicMax winner into win[rep].
    for (int j = t; j < E; j += TPB) win[j] = -1;
    __syncthreads();
    for (int j = t; j < E; j += TPB) {
        int aj = ea[j];
        int rep = j;
        for (int k = 0; k < j; k++)
            if (ea[k] == aj) { rep = k; break; }
        atomicMax(&win[rep], eg[j]);
    }
    __syncthreads();
    for (int j = t; j < E; j += TPB)
        if (win[j] >= 0) out[ea[j]] = (float)win[j];
}

extern "C" void kernel_launch(void* const* d_in, const int* in_sizes, int n_in,
                              void* d_out, int out_size)
{
    const float4* anc = (const float4*)d_in[0];
    const float4* gts = (const float4*)d_in[1];
    int n = in_sizes[0] / 4;
    int m = in_sizes[1] / 4;
    float* out = (float*)d_out;

    void* ptop = nullptr;
    cudaGetSymbolAddress(&ptop, g_top3);

    int nb = (n + TPB - 1) / TPB;
    k_hist<<<nb, TPB>>>(anc, n);
    k_phase2<<<NCELL * 2, TPB>>>(nb, gts, m);
    k_offs<<<1, NCELL>>>();
    k_scatter<<<nb, TPB>>>(anc, n, nb);
    int mblocks = NCELL + (n + CHUNK - 1) / CHUNK;
    k_main<<<mblocks, TPB>>>(gts, out, (unsigned long long*)ptop);
    k2_resolve<<<1, TPB>>>((const unsigned long long*)ptop, m, out);
}

// round 7
// speedup vs baseline: 1.2907x; 1.0650x over previous
#include <cuda_runtime.h>
#include <cstdint>

// S3FD anchor assignment: spatial binning via atomic-free counting sort.
// 4 kernels (ticket-fused):
//   k_hist:    4 anchors/thread: cell id (16x16 grid, 64px cells, by center),
//              per-block smem histogram -> g_blockhist[cell][block]
//   k_phase2:  blocks [0,NCELL): per-cell exclusive scan of block counts;
//              blocks [NCELL,2*NCELL): per-cell GT list (order-preserving ballot
//              compaction -> increasing GT order = reference first-max tie-break)
//              + zero g_top3. LAST block (ticket) scans cell totals -> offsets +
//              builds the 1024-anchor chunk worklist (old k_offs).
//   k_scatter: 4 anchors/thread: smem cursors -> scatter ONLY the 4B anchor idx
//              (g_binned). No box copy: k_main gathers boxes from L2.
//   k_main:    per-chunk IoU vs cell's GT list; max/argmax -> stage-1 assign;
//              per-GT top-3 via lock-free atomicMax cascade (smem -> global).
//              LAST block (ticket) resolves forced claims into out (old k2),
//              reusing dead smem.
// Output dtype float32 (small ints as floats). IoU math uses __f*_rn intrinsics:
// bit-identical to the float32 reference. Pruned pairs always have inter==0 and
// cannot affect strict-> argmax (best init 0) or the iou>0-gated top-3.

#define TPB 256
#define APT 4
#define CHUNK (TPB * APT)      // 1024 anchors per chunk (hist/scatter/main)
#define MAXM 256               // >= n_gt (200)
#define MAXN (1 << 20)         // >= n_anchor (500000)
#define NB_MAX (MAXN / CHUNK)
#define NCELL 256
#define GRIDW 16
#define CELL_PX 64.0f
#define EXPAND 65.0f           // 64 max anchor half-extent + 1px rounding slack

__device__ unsigned char g_cellid[MAXN];
__device__ int g_blockhist[NCELL * NB_MAX];     // cell-major: [cell * nb + block]
__device__ int g_celltotal[NCELL];
__device__ int g_offs[NCELL];
__device__ int g_nwork;
__device__ int4 g_work[NCELL + MAXN / CHUNK + 2];
__device__ int g_binned[MAXN];                  // binned pos -> original anchor idx
__device__ int g_gtcnt[NCELL];
__device__ int g_gtlist[NCELL * MAXM];
__device__ unsigned long long g_top3[MAXM * 3];
__device__ unsigned g_tick1;                    // phase2 ticket (self-resetting)
__device__ unsigned g_tick2;                    // k_main ticket (self-resetting)

// Lock-free top-3 insert: slots monotone non-decreasing under atomicMax; the
// displaced minimum cascades down. Keys distinct (low bits = ~anchor idx), so
// the final state is the exact sorted top-3 of all inserted keys.
__device__ __forceinline__ void cascade_insert(unsigned long long* s, unsigned long long v) {
#pragma unroll
    for (int i = 0; i < 3; i++) {
        unsigned long long old = atomicMax(&s[i], v);
        v = old < v ? old : v;
        if (v == 0ull) return;
    }
}

__device__ __forceinline__ int cell_of(float4 a) {
    int cx = min(GRIDW - 1, max(0, (int)((a.x + a.z) * (0.5f / CELL_PX))));
    int cy = min(GRIDW - 1, max(0, (int)((a.y + a.w) * (0.5f / CELL_PX))));
    return cy * GRIDW + cx;
}

__global__ void __launch_bounds__(TPB) k_hist(const float4* __restrict__ anc, int n) {
    __shared__ int h[NCELL];
    const int t = threadIdx.x, b = blockIdx.x;
    h[t] = 0;
    __syncthreads();
    const int base = b * CHUNK;
#pragma unroll
    for (int k = 0; k < APT; k++) {
        int i = base + k * TPB + t;
        if (i < n) {
            int c = cell_of(anc[i]);
            g_cellid[i] = (unsigned char)c;
            atomicAdd(&h[c], 1);
        }
    }
    __syncthreads();
    g_blockhist[t * gridDim.x + b] = h[t];
}

// Blocks [0,NCELL): per-cell scan. Blocks [NCELL,2*NCELL): GT lists + zero top3.
// Last-finishing block (ticket) computes bin offsets + chunk worklist.
__global__ void __launch_bounds__(TPB) k_phase2(int nb, const float4* __restrict__ gts, int m) {
    __shared__ int sh[TPB];
    const int t = threadIdx.x;
    if (blockIdx.x < NCELL) {
        const int c = blockIdx.x;
        const int per = (nb + TPB - 1) / TPB;
        int* row = &g_blockhist[c * nb];
        int s = 0;
        for (int k = 0; k < per; k++) {
            int idx = t * per + k;
            if (idx < nb) s += row[idx];
        }
        sh[t] = s;
        __syncthreads();
        for (int d = 1; d < TPB; d <<= 1) {
            int x = (t >= d) ? sh[t - d] : 0; __syncthreads();
            sh[t] += x; __syncthreads();
        }
        int run = sh[t] - s;
        for (int k = 0; k < per; k++) {
            int idx = t * per + k;
            if (idx < nb) { int v = row[idx]; row[idx] = run; run += v; }
        }
        if (t == TPB - 1) g_celltotal[c] = sh[t];
    } else {
        const int c = blockIdx.x - NCELL;
        if (c < 3) {
            int i = c * TPB + t;
            if (i < MAXM * 3) g_top3[i] = 0ull;
        }
        float cx0 = (c & (GRIDW - 1)) * CELL_PX - EXPAND;
        float cx1 = (c & (GRIDW - 1)) * CELL_PX + CELL_PX + EXPAND;
        float cy0 = (c >> 4) * CELL_PX - EXPAND;
        float cy1 = (c >> 4) * CELL_PX + CELL_PX + EXPAND;
        bool p = false;
        if (t < m) {
            float4 G = gts[t];
            p = (G.x <= cx1 && G.z >= cx0 && G.y <= cy1 && G.w >= cy0);
        }
        unsigned bl = __ballot_sync(0xffffffffu, p);
        int wid = t >> 5, lane = t & 31;
        int rank = __popc(bl & ((1u << lane) - 1u));
        if (lane == 0) sh[wid] = __popc(bl);
        __syncthreads();
        int base = 0;
        for (int w = 0; w < wid; w++) base += sh[w];
        if (p) g_gtlist[c * MAXM + base + rank] = t;
        if (t == 0) {
            int tot = 0;
            for (int w = 0; w < TPB / 32; w++) tot += sh[w];
            g_gtcnt[c] = tot;
        }
    }

    // ---- ticket: last block builds offsets + worklist (old k_offs) ----
    __syncthreads();
    __threadfence();
    __shared__ unsigned old;
    if (t == 0) old = atomicAdd(&g_tick1, 1u);
    __syncthreads();
    if (old == gridDim.x - 1) {
        int v = __ldcg(&g_celltotal[t]);        // L2-coherent read of peers' writes
        sh[t] = v; __syncthreads();
        for (int d = 1; d < NCELL; d <<= 1) {
            int x = (t >= d) ? sh[t - d] : 0; __syncthreads();
            sh[t] += x; __syncthreads();
        }
        int excl = sh[t] - v;
        g_offs[t] = excl;
        int ch = (v + CHUNK - 1) / CHUNK;
        __syncthreads();
        sh[t] = ch; __syncthreads();
        for (int d = 1; d < NCELL; d <<= 1) {
            int x = (t >= d) ? sh[t - d] : 0; __syncthreads();
            sh[t] += x; __syncthreads();
        }
        int chexcl = sh[t] - ch;
        if (t == NCELL - 1) g_nwork = sh[t];
        for (int k = 0; k < ch; k++)
            g_work[chexcl + k] = make_int4(t, excl + k * CHUNK, min(CHUNK, v - k * CHUNK), 0);
        if (t == 0) g_tick1 = 0;                // reset for next graph replay
    }
}

__global__ void __launch_bounds__(TPB) k_scatter(int n, int nb) {
    __shared__ int cur[NCELL];
    const int t = threadIdx.x, b = blockIdx.x;
    cur[t] = g_offs[t] + g_blockhist[t * nb + b];
    __syncthreads();
    const int base = b * CHUNK;
#pragma unroll
    for (int k = 0; k < APT; k++) {
        int i = base + k * TPB + t;
        if (i < n) {
            int c = g_cellid[i];
            int pos = atomicAdd(&cur[c], 1);
            g_binned[pos] = i;
        }
    }
}

__global__ void __launch_bounds__(TPB) k_main(
    const float4* __restrict__ anc, const float4* __restrict__ gts,
    int m, float* __restrict__ out, unsigned long long* __restrict__ gtop)
{
    __shared__ float4 sgc[MAXM];
    __shared__ float sga[MAXM];
    __shared__ int sgi[MAXM];
    __shared__ unsigned long long stop[MAXM * 3];

    const int tid = threadIdx.x;
    const bool active_blk = blockIdx.x < g_nwork;
    if (active_blk) {
        int4 w = g_work[blockIdx.x];
        const int cell = w.x, astart = w.y, alen = w.z;

        const int cnt = g_gtcnt[cell];
        if (tid < cnt) {
            int gi = g_gtlist[cell * MAXM + tid];
            float4 G = gts[gi];
            sgc[tid] = G;
            sga[tid] = __fmul_rn(__fsub_rn(G.z, G.x), __fsub_rn(G.w, G.y));
            sgi[tid] = gi;
        }
        for (int i = tid; i < cnt * 3; i += TPB) stop[i] = 0ull;
        __syncthreads();

        float ax1[APT], ay1[APT], ax2[APT], ay2[APT], aar[APT], best[APT];
        int bc[APT], aidx[APT];
        bool act[APT];
#pragma unroll
        for (int j = 0; j < APT; j++) {
            int p = tid + j * TPB;
            act[j] = p < alen;
            aidx[j] = act[j] ? g_binned[astart + p] : 0;
            // Gather from L2-resident anchor array; sentinel for inactive lanes.
            float4 a = act[j] ? anc[aidx[j]] : make_float4(4e9f, 4e9f, 4e9f, 4e9f);
            ax1[j] = a.x; ay1[j] = a.y; ax2[j] = a.z; ay2[j] = a.w;
            aar[j] = __fmul_rn(__fsub_rn(a.z, a.x), __fsub_rn(a.w, a.y));
            best[j] = 0.f;   // all-zero row -> ref argmax 0
            bc[j] = 0;
        }

        // Stale-read skip gate: slot-2 high word is monotone non-decreasing; a
        // racy 32-bit read is always a safe lower bound.
        const unsigned* stop_hi = (const unsigned*)stop;

        for (int c = 0; c < cnt; c++) {
            float4 G = sgc[c];
            float ga = sga[c];
            unsigned min_hi = stop_hi[(c * 3 + 2) * 2 + 1];
#pragma unroll
            for (int j = 0; j < APT; j++) {
                float ltx = fmaxf(ax1[j], G.x), lty = fmaxf(ay1[j], G.y);
                float rbx = fminf(ax2[j], G.z), rby = fminf(ay2[j], G.w);
                float wd = fmaxf(__fsub_rn(rbx, ltx), 0.f);
                float ht = fmaxf(__fsub_rn(rby, lty), 0.f);
                float inter = __fmul_rn(wd, ht);
                if (inter > 0.f) {
                    float denom = __fsub_rn(__fadd_rn(aar[j], ga), inter);
                    float iou = __fdiv_rn(inter, denom);   // IEEE rn, matches ref
                    if (iou > best[j]) { best[j] = iou; bc[j] = c; }
                    unsigned ib = __float_as_uint(iou);
                    if (ib >= min_hi) {
                        unsigned long long key =
                            ((unsigned long long)ib << 32) | (unsigned)(~(unsigned)aidx[j]);
                        cascade_insert(&stop[c * 3], key);
                        min_hi = stop_hi[(c * 3 + 2) * 2 + 1];
                    }
                }
            }
        }

#pragma unroll
        for (int j = 0; j < APT; j++) {
            if (act[j]) {
                float r = -2.0f;
                if (best[j] < 0.3f) r = -1.0f;
                if (best[j] > 0.5f) r = (float)sgi[bc[j]];
                out[aidx[j]] = r;
            }
        }

        __syncthreads();
        const unsigned* gtop_hi = (const unsigned*)gtop;
        for (int i = tid; i < cnt * 3; i += TPB) {
            unsigned long long v = stop[i];
            if (!v) continue;
            int orig = sgi[i / 3];
            unsigned gm = gtop_hi[(orig * 3 + 2) * 2 + 1];
            if ((unsigned)(v >> 32) >= gm) cascade_insert(&gtop[orig * 3], v);
        }
    }

    // ---- ticket: last block resolves forced claims (old k2_resolve) ----
    __syncthreads();
    __threadfence();
    __shared__ unsigned old;
    if (tid == 0) old = atomicAdd(&g_tick2, 1u);
    __syncthreads();
    if (old == gridDim.x - 1) {
        // Overlay resolve arrays on dead smem: stop = 1536 ints, sgc = 1024 ints.
        int* ea = (int*)stop;             // [MAXM*3]
        int* eg = ((int*)stop) + MAXM * 3;
        int* win = (int*)sgc;             // [MAXM*3]
        __shared__ int rcnt;
        if (tid == 0) rcnt = 0;
        __syncthreads();
        if (tid < m) {
            unsigned long long s0 = __ldcg(&gtop[tid * 3 + 0]);
            unsigned long long s1 = __ldcg(&gtop[tid * 3 + 1]);
            unsigned long long s2 = __ldcg(&gtop[tid * 3 + 2]);
            float v0 = __uint_as_float((unsigned)(s0 >> 32));
            float v1 = __uint_as_float((unsigned)(s1 >> 32));
            float v2 = __uint_as_float((unsigned)(s2 >> 32));
            int npos = (v0 > 0.5f) + (v1 > 0.5f) + (v2 > 0.5f);
            bool low = npos < 3;
            // k==0 always claims. Empty slot 0 = all-zero row: ref rank0 -> anchor 0.
            int a0 = s0 ? (int)(~(unsigned)s0) : 0;
            int e = atomicAdd(&rcnt, 1); ea[e] = a0; eg[e] = tid;
            if (low) {
                if (s1 && v1 > 0.1f) { e = atomicAdd(&rcnt, 1); ea[e] = (int)(~(unsigned)s1); eg[e] = tid; }
                if (s2 && v2 > 0.1f) { e = atomicAdd(&rcnt, 1); ea[e] = (int)(~(unsigned)s2); eg[e] = tid; }
            }
        }
        __syncthreads();
        const int E = rcnt;
        for (int j = tid; j < E; j += TPB) win[j] = -1;
        __syncthreads();
        // winner per anchor = max claiming gt (reference scatter-max), keyed on
        // the first list occurrence of each anchor.
        for (int j = tid; j < E; j += TPB) {
            int aj = ea[j];
            int rep = j;
            for (int k = 0; k < j; k++)
                if (ea[k] == aj) { rep = k; break; }
            atomicMax(&win[rep], eg[j]);
        }
        __syncthreads();
        for (int j = tid; j < E; j += TPB)
            if (win[j] >= 0) out[ea[j]] = (float)win[j];
        if (tid == 0) g_tick2 = 0;            // reset for next graph replay
    }
}

extern "C" void kernel_launch(void* const* d_in, const int* in_sizes, int n_in,
                              void* d_out, int out_size)
{
    const float4* anc = (const float4*)d_in[0];
    const float4* gts = (const float4*)d_in[1];
    int n = in_sizes[0] / 4;
    int m = in_sizes[1] / 4;
    float* out = (float*)d_out;

    void* ptop = nullptr;
    cudaGetSymbolAddress(&ptop, g_top3);

    int nb = (n + CHUNK - 1) / CHUNK;
    k_hist<<<nb, TPB>>>(anc, n);
    k_phase2<<<NCELL * 2, TPB>>>(nb, gts, m);
    k_scatter<<<nb, TPB>>>(n, nb);
    int mblocks = NCELL + (n + CHUNK - 1) / CHUNK;
    k_main<<<mblocks, TPB>>>(anc, gts, m, out, (unsigned long long*)ptop);
}